// round 14
// baseline (speedup 1.0000x reference)
#include <cuda_runtime.h>
#include <cuda_fp16.h>
#include <math.h>
#include <cstdint>

#define NROWS 8192
#define DDIM  128
#define NTILE (NROWS / 128)               // 64 slabs of 128 rows
#define NCTA  1056                        // sum_{q=0}^{31} (64-2q)

// dynamic smem layout
#define SM_A    0                         // 256 rows x 256B f16 = 65536
#define SM_B    65536                     // 128 rows x 256B f16 = 32768
#define SM_RED  98304                     // 256 f32 row sums
#define SM_REDC 99328                     // 128 f32 col sums
#define SM_TOT  99840

// ---------------- scratch (zero at load; self-resetting across replays) -----
__device__ __half g_h[NROWS * DDIM];
__device__ float  g_denom[NROWS];
__device__ float  g_M[2 * DDIM];
__device__ int    g_ncnt[2];
__device__ float  g_Lpart[NTILE][2];
__device__ int    g_slabcnt[NTILE];
__device__ int    g_slabs;
__device__ int    g_prodtk;               // producer ticket
__device__ int    g_rdy[NTILE];           // 2 => slab rows normalized
__device__ int    g_lblstride;

// ---------------- helpers ----------------------------------------------------
__device__ __forceinline__ uint32_t smem_u32(const void* p) {
    uint32_t a;
    asm("{ .reg .u64 t; cvta.to.shared.u64 t, %1; cvt.u32.u64 %0, t; }" : "=r"(a) : "l"(p));
    return a;
}
__device__ __forceinline__ float ex2f(float x) {
    float r;
    asm("ex2.approx.ftz.f32 %0, %1;" : "=f"(r) : "f"(x));
    return r;
}
__device__ __forceinline__ uint32_t h2exp2(uint32_t x) {
    uint32_t r;
    asm("ex2.approx.f16x2 %0, %1;" : "=r"(r) : "r"(x));
    return r;
}
__device__ __forceinline__ uint32_t h2add(uint32_t a, uint32_t b) {
    uint32_t r;
    asm("add.rn.f16x2 %0, %1, %2;" : "=r"(r) : "r"(a), "r"(b));
    return r;
}
__device__ __forceinline__ float2 h2tof2(uint32_t h) {
    __half2 v = *(__half2*)&h;
    return __half22float2(v);
}
__device__ __forceinline__ void ldsm_x4(uint32_t a, uint32_t& r0, uint32_t& r1,
                                        uint32_t& r2, uint32_t& r3) {
    asm volatile("ldmatrix.sync.aligned.m8n8.x4.shared.b16 {%0,%1,%2,%3}, [%4];"
                 : "=r"(r0), "=r"(r1), "=r"(r2), "=r"(r3) : "r"(a));
}
__device__ __forceinline__ void ldsm_x4t(uint32_t a, uint32_t& r0, uint32_t& r1,
                                         uint32_t& r2, uint32_t& r3) {
    asm volatile("ldmatrix.sync.aligned.m8n8.x4.trans.shared.b16 {%0,%1,%2,%3}, [%4];"
                 : "=r"(r0), "=r"(r1), "=r"(r2), "=r"(r3) : "r"(a));
}
__device__ __forceinline__ void mma16816h(uint32_t* c, uint32_t a0, uint32_t a1,
                                          uint32_t a2, uint32_t a3,
                                          uint32_t b0, uint32_t b1) {
    asm volatile(
        "mma.sync.aligned.m16n8k16.row.col.f16.f16.f16.f16 "
        "{%0,%1}, {%2,%3,%4,%5}, {%6,%7}, {%0,%1};"
        : "+r"(c[0]), "+r"(c[1])
        : "r"(a0), "r"(a1), "r"(a2), "r"(a3), "r"(b0), "r"(b1));
}
__device__ __forceinline__ int get_label(const int* l32, int i) { return l32[i * g_lblstride]; }

// ---------------- single fused kernel ----------------------------------------
__global__ void __launch_bounds__(256, 2) k_main(const float* __restrict__ emb,
                                                 const int* __restrict__ l32,
                                                 float* __restrict__ out) {
    extern __shared__ char smem[];
    uint32_t sb = smem_u32(smem);
    float* red  = (float*)(smem + SM_RED);
    float* redc = (float*)(smem + SM_REDC);

    int tid = threadIdx.x;
    int wid = tid >> 5, lane = tid & 31;

    // ===== Phase 0: producer ticket — first 128 arrivals normalize a chunk ====
    __shared__ int s_pt;
    if (tid == 0) s_pt = atomicAdd(&g_prodtk, 1);
    __syncthreads();
    int pt = s_pt;
    if (pt < 128) {
        const float SQRT_LOG2E = 1.2011224087864498f;
        __shared__ int sdet;
        __shared__ float sM[2 * DDIM];
        __shared__ int   scnt[2];
        if (tid == 0) sdet = 0;
        sM[tid] = 0.0f;
        if (tid < 2) scnt[tid] = 0;
        __syncthreads();
        if (l32[2 * tid + 1] != 0) atomicOr(&sdet, 1);
        __syncthreads();
        int stride = sdet ? 1 : 2;
        if (tid == 0 && pt == 0) g_lblstride = stride;

        if (tid < 64) g_denom[pt * 64 + tid] = 0.0f;

        #pragma unroll
        for (int it = 0; it < 8; it++) {
            int row = pt * 64 + wid * 8 + it;
            float4 v = ((const float4*)(emb + (size_t)row * DDIM))[lane];
            float ss = v.x * v.x + v.y * v.y + v.z * v.z + v.w * v.w;
            #pragma unroll
            for (int o = 16; o; o >>= 1) ss += __shfl_xor_sync(0xffffffffu, ss, o);
            float r = rsqrtf(ss);
            int d = lane * 4;
            float e0 = v.x * r, e1 = v.y * r, e2 = v.z * r, e3 = v.w * r;
            float s = r * SQRT_LOG2E;
            __half2 h01 = __floats2half2_rn(v.x * s, v.y * s);
            __half2 h23 = __floats2half2_rn(v.z * s, v.w * s);
            *(__half2*)&g_h[(size_t)row * DDIM + d]     = h01;
            *(__half2*)&g_h[(size_t)row * DDIM + d + 2] = h23;
            int c = (l32[row * stride] == 0) ? 0 : 1;
            if (lane == 0) atomicAdd(&scnt[c], 1);
            float* sMc = &sM[c * DDIM + d];
            atomicAdd(&sMc[0], e0);
            atomicAdd(&sMc[1], e1);
            atomicAdd(&sMc[2], e2);
            atomicAdd(&sMc[3], e3);
        }
        __syncthreads();
        atomicAdd(&g_M[tid], sM[tid]);
        if (tid < 2) atomicAdd(&g_ncnt[tid], scnt[tid]);
        __threadfence();
        __syncthreads();
        if (tid == 0) atomicAdd(&g_rdy[pt >> 1], 1);
    }

    // ===== decode compact triangular index -> (bi2, bj), bj >= 2*bi2 =========
    int rem = blockIdx.x, q = 0;
    while (rem >= 64 - 2 * q) { rem -= 64 - 2 * q; q++; }
    int bi2 = q, bj = 2 * q + rem;
    int i0 = bi2 * 256, j0 = bj * 128;
    bool has_j = (bj != 2 * bi2);

    // ===== wait for the 3 slabs this tile needs ==============================
    if (tid == 0) {
        while (atomicAdd(&g_rdy[2 * bi2], 0) < 2)     __nanosleep(128);
        while (atomicAdd(&g_rdy[2 * bi2 + 1], 0) < 2) __nanosleep(128);
        while (atomicAdd(&g_rdy[bj], 0) < 2)          __nanosleep(128);
    }
    __syncthreads();

    red[tid] = 0.0f;
    if (tid < 128) redc[tid] = 0.0f;

    // ===== tile loads (16B chunk c of row r stored at chunk c^(r&7)) =========
    {
        const uint4* arow = (const uint4*)&g_h[(size_t)(i0 + tid) * DDIM];
        #pragma unroll
        for (int c = 0; c < 16; c++) {
            uint32_t off = tid * 256 + ((c ^ (tid & 7)) << 4);
            *(uint4*)(smem + SM_A + off) = arow[c];
        }
        int row = tid >> 1, half = tid & 1;
        const uint4* brow = (const uint4*)&g_h[(size_t)(j0 + row) * DDIM];
        #pragma unroll
        for (int c = 0; c < 8; c++) {
            int chunk = half * 8 + c;
            uint32_t off = row * 256 + ((chunk ^ (row & 7)) << 4);
            *(uint4*)(smem + SM_B + off) = brow[chunk];
        }
    }
    __syncthreads();

    int mg = wid >> 1, ng = wid & 1;
    int m_off = mg * 64, n_off = ng * 64;
    int h = mg >> 1;
    bool skip = (bj == 2 * bi2) && (h == 1);
    bool diag = (2 * bi2 + h == bj);

    if (!skip) {
        uint32_t acc[4][8][2];
        #pragma unroll
        for (int mt = 0; mt < 4; mt++)
            #pragma unroll
            for (int nt = 0; nt < 8; nt++) { acc[mt][nt][0] = 0u; acc[mt][nt][1] = 0u; }

        uint32_t rowA = (uint32_t)(m_off + (lane & 15));
        uint32_t rowBbase = (uint32_t)(n_off + ((lane >> 4) << 3) + (lane & 7));
        uint32_t chA_sel = (uint32_t)(lane >> 4);
        uint32_t chB_sel = (uint32_t)((lane >> 3) & 1);

        #pragma unroll
        for (int kk = 0; kk < 8; kk++) {
            uint32_t a[4][4];
            #pragma unroll
            for (int mt = 0; mt < 4; mt++) {
                uint32_t r = rowA + mt * 16;
                uint32_t chunk = (uint32_t)(kk * 2) + chA_sel;
                uint32_t addr = sb + SM_A + r * 256 + ((chunk ^ (r & 7)) << 4);
                ldsm_x4(addr, a[mt][0], a[mt][1], a[mt][2], a[mt][3]);
            }
            uint32_t b[8][2];
            #pragma unroll
            for (int p = 0; p < 4; p++) {
                uint32_t r = rowBbase + (uint32_t)(p * 16);
                uint32_t chunk = (uint32_t)(kk * 2) + chB_sel;
                uint32_t addr = sb + SM_B + r * 256 + ((chunk ^ (r & 7)) << 4);
                ldsm_x4t(addr, b[2 * p][0], b[2 * p][1], b[2 * p + 1][0], b[2 * p + 1][1]);
            }
            #pragma unroll
            for (int mt = 0; mt < 4; mt++)
                #pragma unroll
                for (int nt = 0; nt < 8; nt++)
                    mma16816h(acc[mt][nt], a[mt][0], a[mt][1], a[mt][2], a[mt][3],
                              b[nt][0], b[nt][1]);
        }

        int lrow = lane >> 2;
        int lcol = (lane & 3) * 2;

        if (!diag) {
            // ---- f16x2 epilogue (half the MUFU ops) ----
            uint32_t colp[8];
            #pragma unroll
            for (int nt = 0; nt < 8; nt++) colp[nt] = 0u;
            #pragma unroll
            for (int mt = 0; mt < 4; mt++) {
                uint32_t rp0 = 0u, rp1 = 0u;
                #pragma unroll
                for (int nt = 0; nt < 8; nt++) {
                    uint32_t e0 = h2exp2(acc[mt][nt][0]);
                    uint32_t e1 = h2exp2(acc[mt][nt][1]);
                    rp0 = h2add(rp0, e0);
                    rp1 = h2add(rp1, e1);
                    colp[nt] = h2add(colp[nt], h2add(e0, e1));
                }
                float2 f0 = h2tof2(rp0);
                float2 f1 = h2tof2(rp1);
                float s0 = f0.x + f0.y;
                float s1 = f1.x + f1.y;
                s0 += __shfl_xor_sync(0xffffffffu, s0, 1);
                s0 += __shfl_xor_sync(0xffffffffu, s0, 2);
                s1 += __shfl_xor_sync(0xffffffffu, s1, 1);
                s1 += __shfl_xor_sync(0xffffffffu, s1, 2);
                if ((lane & 3) == 0) {
                    atomicAdd(&red[m_off + mt * 16 + lrow], s0);
                    atomicAdd(&red[m_off + mt * 16 + lrow + 8], s1);
                }
            }
            #pragma unroll
            for (int nt = 0; nt < 8; nt++) {
                float2 cf = h2tof2(colp[nt]);
                #pragma unroll
                for (int hh = 0; hh < 2; hh++) {
                    float c = hh ? cf.y : cf.x;
                    c += __shfl_xor_sync(0xffffffffu, c, 4);
                    c += __shfl_xor_sync(0xffffffffu, c, 8);
                    c += __shfl_xor_sync(0xffffffffu, c, 16);
                    if (lane < 4)
                        atomicAdd(&redc[n_off + nt * 8 + (lane & 3) * 2 + hh], c);
                }
            }
        } else {
            // ---- diag slow path: fp32 with exact masking (no col sums) ----
            #pragma unroll
            for (int mt = 0; mt < 4; mt++) {
                float s0 = 0.0f, s1 = 0.0f;
                int grow0 = i0 + m_off + mt * 16 + lrow;
                #pragma unroll
                for (int nt = 0; nt < 8; nt++) {
                    int gcol = j0 + n_off + nt * 8 + lcol;
                    float2 f0 = h2tof2(acc[mt][nt][0]);
                    float2 f1 = h2tof2(acc[mt][nt][1]);
                    float e0 = ex2f(f0.x), e1 = ex2f(f0.y);
                    float e2 = ex2f(f1.x), e3 = ex2f(f1.y);
                    if (gcol     == grow0)     e0 = 0.0f;
                    if (gcol + 1 == grow0)     e1 = 0.0f;
                    if (gcol     == grow0 + 8) e2 = 0.0f;
                    if (gcol + 1 == grow0 + 8) e3 = 0.0f;
                    s0 += e0 + e1;
                    s1 += e2 + e3;
                }
                s0 += __shfl_xor_sync(0xffffffffu, s0, 1);
                s0 += __shfl_xor_sync(0xffffffffu, s0, 2);
                s1 += __shfl_xor_sync(0xffffffffu, s1, 1);
                s1 += __shfl_xor_sync(0xffffffffu, s1, 2);
                if ((lane & 3) == 0) {
                    atomicAdd(&red[m_off + mt * 16 + lrow], s0);
                    atomicAdd(&red[m_off + mt * 16 + lrow + 8], s1);
                }
            }
        }
    }

    __syncthreads();
    atomicAdd(&g_denom[i0 + tid], red[tid]);
    if (tid < 128 && has_j)
        atomicAdd(&g_denom[j0 + tid], redc[tid]);
    __syncthreads();

    // ===== slab tickets: thr(s) = 64 - (s>>1) contributions ==================
    __shared__ int sfin[3];
    __shared__ float wred[8];
    int slabs_of[3] = { 2 * bi2, 2 * bi2 + 1, bj };
    if (tid == 0) {
        __threadfence();
        sfin[0] = (atomicAdd(&g_slabcnt[2 * bi2], 1) == (64 - bi2) - 1) ? 1 : 0;
        sfin[1] = 0; sfin[2] = 0;
        if (has_j) {
            sfin[1] = (atomicAdd(&g_slabcnt[2 * bi2 + 1], 1) == (64 - bi2) - 1) ? 1 : 0;
            sfin[2] = (atomicAdd(&g_slabcnt[bj], 1) == (64 - (bj >> 1)) - 1) ? 1 : 0;
        }
    }
    __syncthreads();
    int nfin = sfin[0] + sfin[1] + sfin[2];
    if (nfin == 0) return;

    __threadfence();
    #pragma unroll
    for (int which = 0; which < 3; which++) {
        if (!sfin[which]) continue;
        int s = slabs_of[which];
        float l0 = 0.0f, l1 = 0.0f;
        if (tid < 128) {
            int row = s * 128 + tid;
            float li = logf(g_denom[row]);
            if (get_label(l32, row) == 0) l0 = li; else l1 = li;
        }
        #pragma unroll
        for (int o = 16; o; o >>= 1) {
            l0 += __shfl_xor_sync(0xffffffffu, l0, o);
            l1 += __shfl_xor_sync(0xffffffffu, l1, o);
        }
        if (lane == 0 && wid < 4) { wred[wid] = l0; wred[wid + 4] = l1; }
        __syncthreads();
        if (tid == 0) {
            g_Lpart[s][0] = wred[0] + wred[1] + wred[2] + wred[3];
            g_Lpart[s][1] = wred[4] + wred[5] + wred[6] + wred[7];
            g_slabcnt[s] = 0;
        }
        __syncthreads();
    }

    // ===== final ticket: assemble loss + reset all counters ==================
    __shared__ int s_final;
    if (tid == 0) {
        __threadfence();
        int old = atomicAdd(&g_slabs, nfin);
        s_final = (old + nfin == NTILE) ? 1 : 0;
        if (s_final) g_slabs = 0;
    }
    __syncthreads();
    if (!s_final) return;
    __threadfence();

    __shared__ float sm0[8], sm1[8], sL0[8], sL1[8];
    float Md = g_M[tid];
    g_M[tid] = 0.0f;
    if (tid < NTILE) g_rdy[tid] = 0;
    if (tid == 0) g_prodtk = 0;
    float q0 = (tid < 128) ? Md * Md : 0.0f;
    float q1 = (tid < 128) ? 0.0f : Md * Md;
    #pragma unroll
    for (int o = 16; o; o >>= 1) {
        q0 += __shfl_xor_sync(0xffffffffu, q0, o);
        q1 += __shfl_xor_sync(0xffffffffu, q1, o);
    }
    if (lane == 0) { sm0[wid] = q0; sm1[wid] = q1; }
    float L0 = 0.0f, L1 = 0.0f;
    if (tid < NTILE) { L0 = g_Lpart[tid][0]; L1 = g_Lpart[tid][1]; }
    #pragma unroll
    for (int o = 16; o; o >>= 1) {
        L0 += __shfl_xor_sync(0xffffffffu, L0, o);
        L1 += __shfl_xor_sync(0xffffffffu, L1, o);
    }
    if (lane == 0) { sL0[wid] = L0; sL1[wid] = L1; }
    __syncthreads();
    if (tid == 0) {
        float M0 = 0.0f, M1 = 0.0f, TL0 = 0.0f, TL1 = 0.0f;
        #pragma unroll
        for (int w = 0; w < 8; w++) {
            M0 += sm0[w]; M1 += sm1[w];
            TL0 += sL0[w]; TL1 += sL1[w];
        }
        float n0 = (float)g_ncnt[0], n1 = (float)g_ncnt[1];
        g_ncnt[0] = 0; g_ncnt[1] = 0;
        float loss0 = -M0 + n0 + (n0 - 1.0f) * TL0;
        float loss1 = -M1 + n1 + (n1 - 1.0f) * TL1;
        out[0] = loss0 / n0 + loss1;
    }
}

// ---------------- launch -----------------------------------------------------
extern "C" void kernel_launch(void* const* d_in, const int* in_sizes, int n_in,
                              void* d_out, int out_size) {
    const float* emb = (const float*)d_in[0];
    const int*   l32 = (const int*)d_in[1];
    float*       out = (float*)d_out;

    cudaFuncSetAttribute(k_main, cudaFuncAttributeMaxDynamicSharedMemorySize, SM_TOT);
    k_main<<<NCTA, 256, SM_TOT>>>(emb, l32, out);
}

// round 15
// speedup vs baseline: 1.0831x; 1.0831x over previous
#include <cuda_runtime.h>
#include <cuda_fp16.h>
#include <math.h>
#include <cstdint>

#define NROWS 8192
#define DDIM  128
#define NTILE (NROWS / 128)               // 64 slabs of 128 rows

// dynamic smem layout for k_sim
#define SM_A    0                         // 256 rows x 256B f16 = 65536
#define SM_B    65536                     // 128 rows x 256B f16 = 32768
#define SM_RED  98304                     // 256 f32 row sums
#define SM_REDC 99328                     // 128 f32 col sums
#define SM_TOT  99840

// ---------------- scratch (init-free or self-resetting) ---------------------
__device__ __half g_h[NROWS * DDIM];      // normalized * sqrt(log2e), f16
__device__ float  g_denom[NROWS];         // zeroed by k_normalize each run
__device__ float  g_M[2 * DDIM];          // class sums; reset by final finisher
__device__ int    g_ncnt[2];              // class counts; reset by final finisher
__device__ float  g_Lpart[NTILE][2];      // per-slab gated log sums
__device__ int    g_slabcnt[NTILE];       // reset by slab finisher
__device__ int    g_slabs;                // reset by final finisher
__device__ int    g_lblstride;

// ---------------- helpers ----------------------------------------------------
__device__ __forceinline__ uint32_t smem_u32(const void* p) {
    uint32_t a;
    asm("{ .reg .u64 t; cvta.to.shared.u64 t, %1; cvt.u32.u64 %0, t; }" : "=r"(a) : "l"(p));
    return a;
}
__device__ __forceinline__ float ex2f(float x) {
    float r;
    asm("ex2.approx.ftz.f32 %0, %1;" : "=f"(r) : "f"(x));
    return r;
}
__device__ __forceinline__ uint32_t h2exp2(uint32_t x) {
    uint32_t r;
    asm("ex2.approx.f16x2 %0, %1;" : "=r"(r) : "r"(x));
    return r;
}
__device__ __forceinline__ uint32_t h2add(uint32_t a, uint32_t b) {
    uint32_t r;
    asm("add.rn.f16x2 %0, %1, %2;" : "=r"(r) : "r"(a), "r"(b));
    return r;
}
__device__ __forceinline__ float2 h2tof2(uint32_t h) {
    __half2 v = *(__half2*)&h;
    return __half22float2(v);
}
__device__ __forceinline__ void ldsm_x4(uint32_t a, uint32_t& r0, uint32_t& r1,
                                        uint32_t& r2, uint32_t& r3) {
    asm volatile("ldmatrix.sync.aligned.m8n8.x4.shared.b16 {%0,%1,%2,%3}, [%4];"
                 : "=r"(r0), "=r"(r1), "=r"(r2), "=r"(r3) : "r"(a));
}
__device__ __forceinline__ void ldsm_x4t(uint32_t a, uint32_t& r0, uint32_t& r1,
                                         uint32_t& r2, uint32_t& r3) {
    asm volatile("ldmatrix.sync.aligned.m8n8.x4.trans.shared.b16 {%0,%1,%2,%3}, [%4];"
                 : "=r"(r0), "=r"(r1), "=r"(r2), "=r"(r3) : "r"(a));
}
__device__ __forceinline__ void mma16816h(uint32_t* c, uint32_t a0, uint32_t a1,
                                          uint32_t a2, uint32_t a3,
                                          uint32_t b0, uint32_t b1) {
    asm volatile(
        "mma.sync.aligned.m16n8k16.row.col.f16.f16.f16.f16 "
        "{%0,%1}, {%2,%3,%4,%5}, {%6,%7}, {%0,%1};"
        : "+r"(c[0]), "+r"(c[1])
        : "r"(a0), "r"(a1), "r"(a2), "r"(a3), "r"(b0), "r"(b1));
}
__device__ __forceinline__ int get_label(const int* l32, int i) { return l32[i * g_lblstride]; }

// ---------------- K1: normalize -> f16*sqrt(log2e) + class sums + resets ----
// 128 blocks x 256 threads; block b owns rows [64b, 64b+64).
__global__ void __launch_bounds__(256) k_normalize(const float* __restrict__ emb,
                                                   const int* __restrict__ l32) {
    const float SQRT_LOG2E = 1.2011224087864498f;
    int tid = threadIdx.x;
    int wid = tid >> 5, lane = tid & 31;
    int b = blockIdx.x;

    __shared__ int sdet;
    __shared__ float sM[2 * DDIM];
    __shared__ int   scnt[2];
    if (tid == 0) sdet = 0;
    sM[tid] = 0.0f;
    if (tid < 2) scnt[tid] = 0;
    __syncthreads();
    // labels are 0/1; int64 LE => odd int32 words are 0 (reads ints [1..511])
    if (l32[2 * tid + 1] != 0) atomicOr(&sdet, 1);
    __syncthreads();
    int stride = sdet ? 1 : 2;
    if (tid == 0 && b == 0) g_lblstride = stride;

    if (tid < 64) g_denom[b * 64 + tid] = 0.0f;

    #pragma unroll
    for (int it = 0; it < 8; it++) {
        int row = b * 64 + wid * 8 + it;
        float4 v = ((const float4*)(emb + (size_t)row * DDIM))[lane];
        float ss = v.x * v.x + v.y * v.y + v.z * v.z + v.w * v.w;
        #pragma unroll
        for (int o = 16; o; o >>= 1) ss += __shfl_xor_sync(0xffffffffu, ss, o);
        float r = rsqrtf(ss);
        int d = lane * 4;
        float e0 = v.x * r, e1 = v.y * r, e2 = v.z * r, e3 = v.w * r;
        float s = r * SQRT_LOG2E;
        __half2 h01 = __floats2half2_rn(v.x * s, v.y * s);
        __half2 h23 = __floats2half2_rn(v.z * s, v.w * s);
        *(__half2*)&g_h[(size_t)row * DDIM + d]     = h01;
        *(__half2*)&g_h[(size_t)row * DDIM + d + 2] = h23;
        int c = (l32[row * stride] == 0) ? 0 : 1;
        if (lane == 0) atomicAdd(&scnt[c], 1);
        float* sMc = &sM[c * DDIM + d];
        atomicAdd(&sMc[0], e0);
        atomicAdd(&sMc[1], e1);
        atomicAdd(&sMc[2], e2);
        atomicAdd(&sMc[3], e3);
    }
    __syncthreads();
    atomicAdd(&g_M[tid], sM[tid]);
    if (tid < 2) atomicAdd(&g_ncnt[tid], scnt[tid]);
}

// ---------------- K2: f16 HMMA, CTA 256(m)x128(n) + distributed loss tails ---
// grid (bj, bi2), valid when bj >= 2*bi2. Halves h=0,1 are i-tiles 2*bi2+h.
// 8 warps as 4(m) x 2(n), warp tile 64x64, f16 accumulators.
// Non-diag epilogue: ex2.approx.f16x2 on acc (half the MUFU ops vs fp32).
__global__ void __launch_bounds__(256, 2) k_sim(const int* __restrict__ l32,
                                                float* __restrict__ out) {
    int bj = blockIdx.x, bi2 = blockIdx.y;
    if (bj < 2 * bi2) return;

    extern __shared__ char smem[];
    uint32_t sb = smem_u32(smem);
    float* red  = (float*)(smem + SM_RED);
    float* redc = (float*)(smem + SM_REDC);

    int tid = threadIdx.x;
    int wid = tid >> 5, lane = tid & 31;
    int i0 = bi2 * 256, j0 = bj * 128;

    red[tid] = 0.0f;
    if (tid < 128) redc[tid] = 0.0f;

    // ---- tile loads (16B chunk c of row r stored at chunk c^(r&7)) ----
    {
        const uint4* arow = (const uint4*)&g_h[(size_t)(i0 + tid) * DDIM];
        #pragma unroll
        for (int c = 0; c < 16; c++) {
            uint32_t off = tid * 256 + ((c ^ (tid & 7)) << 4);
            *(uint4*)(smem + SM_A + off) = arow[c];
        }
        int row = tid >> 1, half = tid & 1;
        const uint4* brow = (const uint4*)&g_h[(size_t)(j0 + row) * DDIM];
        #pragma unroll
        for (int c = 0; c < 8; c++) {
            int chunk = half * 8 + c;
            uint32_t off = row * 256 + ((chunk ^ (row & 7)) << 4);
            *(uint4*)(smem + SM_B + off) = brow[chunk];
        }
    }
    __syncthreads();

    int mg = wid >> 1, ng = wid & 1;
    int m_off = mg * 64, n_off = ng * 64;
    int h = mg >> 1;
    bool skip = (bj == 2 * bi2) && (h == 1);
    bool diag = (2 * bi2 + h == bj);

    if (!skip) {
        uint32_t acc[4][8][2];
        #pragma unroll
        for (int mt = 0; mt < 4; mt++)
            #pragma unroll
            for (int nt = 0; nt < 8; nt++) { acc[mt][nt][0] = 0u; acc[mt][nt][1] = 0u; }

        uint32_t rowA = (uint32_t)(m_off + (lane & 15));
        uint32_t rowBbase = (uint32_t)(n_off + ((lane >> 4) << 3) + (lane & 7));
        uint32_t chA_sel = (uint32_t)(lane >> 4);
        uint32_t chB_sel = (uint32_t)((lane >> 3) & 1);

        #pragma unroll
        for (int kk = 0; kk < 8; kk++) {
            uint32_t a[4][4];
            #pragma unroll
            for (int mt = 0; mt < 4; mt++) {
                uint32_t r = rowA + mt * 16;
                uint32_t chunk = (uint32_t)(kk * 2) + chA_sel;
                uint32_t addr = sb + SM_A + r * 256 + ((chunk ^ (r & 7)) << 4);
                ldsm_x4(addr, a[mt][0], a[mt][1], a[mt][2], a[mt][3]);
            }
            uint32_t b[8][2];
            #pragma unroll
            for (int p = 0; p < 4; p++) {
                uint32_t r = rowBbase + (uint32_t)(p * 16);
                uint32_t chunk = (uint32_t)(kk * 2) + chB_sel;
                uint32_t addr = sb + SM_B + r * 256 + ((chunk ^ (r & 7)) << 4);
                ldsm_x4t(addr, b[2 * p][0], b[2 * p][1], b[2 * p + 1][0], b[2 * p + 1][1]);
            }
            #pragma unroll
            for (int mt = 0; mt < 4; mt++)
                #pragma unroll
                for (int nt = 0; nt < 8; nt++)
                    mma16816h(acc[mt][nt], a[mt][0], a[mt][1], a[mt][2], a[mt][3],
                              b[nt][0], b[nt][1]);
        }

        int lrow = lane >> 2;
        int lcol = (lane & 3) * 2;

        if (!diag) {
            // ---- f16x2 epilogue: ex2 on both halves, half2 partial sums ----
            uint32_t colp[8];
            #pragma unroll
            for (int nt = 0; nt < 8; nt++) colp[nt] = 0u;
            #pragma unroll
            for (int mt = 0; mt < 4; mt++) {
                uint32_t rp0 = 0u, rp1 = 0u;
                #pragma unroll
                for (int nt = 0; nt < 8; nt++) {
                    uint32_t e0 = h2exp2(acc[mt][nt][0]);
                    uint32_t e1 = h2exp2(acc[mt][nt][1]);
                    rp0 = h2add(rp0, e0);
                    rp1 = h2add(rp1, e1);
                    colp[nt] = h2add(colp[nt], h2add(e0, e1));
                }
                float2 f0 = h2tof2(rp0);
                float2 f1 = h2tof2(rp1);
                float s0 = f0.x + f0.y;
                float s1 = f1.x + f1.y;
                s0 += __shfl_xor_sync(0xffffffffu, s0, 1);
                s0 += __shfl_xor_sync(0xffffffffu, s0, 2);
                s1 += __shfl_xor_sync(0xffffffffu, s1, 1);
                s1 += __shfl_xor_sync(0xffffffffu, s1, 2);
                if ((lane & 3) == 0) {
                    atomicAdd(&red[m_off + mt * 16 + lrow], s0);
                    atomicAdd(&red[m_off + mt * 16 + lrow + 8], s1);
                }
            }
            #pragma unroll
            for (int nt = 0; nt < 8; nt++) {
                float2 cf = h2tof2(colp[nt]);
                #pragma unroll
                for (int hh = 0; hh < 2; hh++) {
                    float c = hh ? cf.y : cf.x;
                    c += __shfl_xor_sync(0xffffffffu, c, 4);
                    c += __shfl_xor_sync(0xffffffffu, c, 8);
                    c += __shfl_xor_sync(0xffffffffu, c, 16);
                    if (lane < 4)
                        atomicAdd(&redc[n_off + nt * 8 + (lane & 3) * 2 + hh], c);
                }
            }
        } else {
            // ---- diag slow path: fp32 with exact masking (no col sums) ----
            #pragma unroll
            for (int mt = 0; mt < 4; mt++) {
                float s0 = 0.0f, s1 = 0.0f;
                int grow0 = i0 + m_off + mt * 16 + lrow;
                #pragma unroll
                for (int nt = 0; nt < 8; nt++) {
                    int gcol = j0 + n_off + nt * 8 + lcol;
                    float2 f0 = h2tof2(acc[mt][nt][0]);
                    float2 f1 = h2tof2(acc[mt][nt][1]);
                    float e0 = ex2f(f0.x), e1 = ex2f(f0.y);
                    float e2 = ex2f(f1.x), e3 = ex2f(f1.y);
                    if (gcol     == grow0)     e0 = 0.0f;
                    if (gcol + 1 == grow0)     e1 = 0.0f;
                    if (gcol     == grow0 + 8) e2 = 0.0f;
                    if (gcol + 1 == grow0 + 8) e3 = 0.0f;
                    s0 += e0 + e1;
                    s1 += e2 + e3;
                }
                s0 += __shfl_xor_sync(0xffffffffu, s0, 1);
                s0 += __shfl_xor_sync(0xffffffffu, s0, 2);
                s1 += __shfl_xor_sync(0xffffffffu, s1, 1);
                s1 += __shfl_xor_sync(0xffffffffu, s1, 2);
                if ((lane & 3) == 0) {
                    atomicAdd(&red[m_off + mt * 16 + lrow], s0);
                    atomicAdd(&red[m_off + mt * 16 + lrow + 8], s1);
                }
            }
        }
    }

    __syncthreads();
    atomicAdd(&g_denom[i0 + tid], red[tid]);
    bool has_j = (bj != 2 * bi2);
    if (tid < 128 && has_j)
        atomicAdd(&g_denom[j0 + tid], redc[tid]);
    __syncthreads();                    // denom atomics issued before tickets

    // ---- slab tickets: thr(s) = 64 - (s>>1) contributions ----
    __shared__ int sfin[3];
    __shared__ float wred[8];
    int slabs_of[3] = { 2 * bi2, 2 * bi2 + 1, bj };
    if (tid == 0) {
        __threadfence();
        sfin[0] = (atomicAdd(&g_slabcnt[2 * bi2], 1) == (64 - bi2) - 1) ? 1 : 0;
        sfin[1] = 0; sfin[2] = 0;
        if (has_j) {
            sfin[1] = (atomicAdd(&g_slabcnt[2 * bi2 + 1], 1) == (64 - bi2) - 1) ? 1 : 0;
            sfin[2] = (atomicAdd(&g_slabcnt[bj], 1) == (64 - (bj >> 1)) - 1) ? 1 : 0;
        }
    }
    __syncthreads();
    int nfin = sfin[0] + sfin[1] + sfin[2];
    if (nfin == 0) return;

    __threadfence();                    // acquire: slab contributions visible
    #pragma unroll
    for (int which = 0; which < 3; which++) {
        if (!sfin[which]) continue;
        int s = slabs_of[which];
        float l0 = 0.0f, l1 = 0.0f;
        if (tid < 128) {
            int row = s * 128 + tid;
            float li = logf(g_denom[row]);
            if (get_label(l32, row) == 0) l0 = li; else l1 = li;
        }
        #pragma unroll
        for (int o = 16; o; o >>= 1) {
            l0 += __shfl_xor_sync(0xffffffffu, l0, o);
            l1 += __shfl_xor_sync(0xffffffffu, l1, o);
        }
        if (lane == 0 && wid < 4) { wred[wid] = l0; wred[wid + 4] = l1; }
        __syncthreads();
        if (tid == 0) {
            g_Lpart[s][0] = wred[0] + wred[1] + wred[2] + wred[3];
            g_Lpart[s][1] = wred[4] + wred[5] + wred[6] + wred[7];
            g_slabcnt[s] = 0;                      // self-reset for next replay
        }
        __syncthreads();
    }

    // ---- final ticket: assemble loss ----
    __shared__ int s_final;
    if (tid == 0) {
        __threadfence();
        int old = atomicAdd(&g_slabs, nfin);
        s_final = (old + nfin == NTILE) ? 1 : 0;
        if (s_final) g_slabs = 0;                  // self-reset
    }
    __syncthreads();
    if (!s_final) return;
    __threadfence();

    __shared__ float sm0[8], sm1[8], sL0[8], sL1[8];
    float Md = g_M[tid];
    g_M[tid] = 0.0f;                               // self-reset
    float q0 = (tid < 128) ? Md * Md : 0.0f;
    float q1 = (tid < 128) ? 0.0f : Md * Md;
    #pragma unroll
    for (int o = 16; o; o >>= 1) {
        q0 += __shfl_xor_sync(0xffffffffu, q0, o);
        q1 += __shfl_xor_sync(0xffffffffu, q1, o);
    }
    if (lane == 0) { sm0[wid] = q0; sm1[wid] = q1; }
    float L0 = 0.0f, L1 = 0.0f;
    if (tid < NTILE) { L0 = g_Lpart[tid][0]; L1 = g_Lpart[tid][1]; }
    #pragma unroll
    for (int o = 16; o; o >>= 1) {
        L0 += __shfl_xor_sync(0xffffffffu, L0, o);
        L1 += __shfl_xor_sync(0xffffffffu, L1, o);
    }
    if (lane == 0) { sL0[wid] = L0; sL1[wid] = L1; }
    __syncthreads();
    if (tid == 0) {
        float M0 = 0.0f, M1 = 0.0f, TL0 = 0.0f, TL1 = 0.0f;
        #pragma unroll
        for (int w = 0; w < 8; w++) {
            M0 += sm0[w]; M1 += sm1[w];
            TL0 += sL0[w]; TL1 += sL1[w];
        }
        float n0 = (float)g_ncnt[0], n1 = (float)g_ncnt[1];
        g_ncnt[0] = 0; g_ncnt[1] = 0;              // self-reset
        float loss0 = -M0 + n0 + (n0 - 1.0f) * TL0;
        float loss1 = -M1 + n1 + (n1 - 1.0f) * TL1;
        out[0] = loss0 / n0 + loss1;
    }
}

// ---------------- launch -----------------------------------------------------
extern "C" void kernel_launch(void* const* d_in, const int* in_sizes, int n_in,
                              void* d_out, int out_size) {
    const float* emb = (const float*)d_in[0];
    const int*   l32 = (const int*)d_in[1];
    float*       out = (float*)d_out;

    cudaFuncSetAttribute(k_sim, cudaFuncAttributeMaxDynamicSharedMemorySize, SM_TOT);

    k_normalize<<<128, 256>>>(emb, l32);
    dim3 grid(64, 32);                 // bj, bi2; invalid CTAs exit immediately
    k_sim<<<grid, 256, SM_TOT>>>(l32, out);
}

// round 16
// speedup vs baseline: 1.1113x; 1.0260x over previous
#include <cuda_runtime.h>
#include <cuda_fp16.h>
#include <math.h>
#include <cstdint>

#define NROWS 8192
#define DDIM  128
#define NTILE (NROWS / 128)               // 64 slabs of 128 rows

// dynamic smem layout for k_sim
#define SM_A    0                         // 256 rows x 256B f16 = 65536
#define SM_B    65536                     // 128 rows x 256B f16 = 32768
#define SM_RED  98304                     // 256 f32 row sums
#define SM_REDC 99328                     // 128 f32 col sums
#define SM_TOT  99840

// ---------------- scratch (init-free or self-resetting) ---------------------
__device__ __half g_h[NROWS * DDIM];      // normalized * sqrt(log2e), f16
__device__ float  g_denom[NROWS];         // zeroed by k_normalize each run
__device__ float  g_M[2 * DDIM];          // class sums; reset by final finisher
__device__ int    g_ncnt[2];              // class counts; reset by final finisher
__device__ float  g_Lpart[NTILE][2];      // per-slab gated log sums
__device__ int    g_slabcnt[NTILE];       // reset by slab finisher
__device__ int    g_slabs;                // reset by final finisher
__device__ int    g_lblstride;

// ---------------- helpers ----------------------------------------------------
__device__ __forceinline__ uint32_t smem_u32(const void* p) {
    uint32_t a;
    asm("{ .reg .u64 t; cvta.to.shared.u64 t, %1; cvt.u32.u64 %0, t; }" : "=r"(a) : "l"(p));
    return a;
}
__device__ __forceinline__ float ex2f(float x) {
    float r;
    asm("ex2.approx.ftz.f32 %0, %1;" : "=f"(r) : "f"(x));
    return r;
}
__device__ __forceinline__ uint32_t h2exp2(uint32_t x) {
    uint32_t r;
    asm("ex2.approx.f16x2 %0, %1;" : "=r"(r) : "r"(x));
    return r;
}
__device__ __forceinline__ uint32_t h2add(uint32_t a, uint32_t b) {
    uint32_t r;
    asm("add.rn.f16x2 %0, %1, %2;" : "=r"(r) : "r"(a), "r"(b));
    return r;
}
__device__ __forceinline__ float2 h2tof2(uint32_t h) {
    __half2 v = *(__half2*)&h;
    return __half22float2(v);
}
__device__ __forceinline__ void ldsm_x4(uint32_t a, uint32_t& r0, uint32_t& r1,
                                        uint32_t& r2, uint32_t& r3) {
    asm volatile("ldmatrix.sync.aligned.m8n8.x4.shared.b16 {%0,%1,%2,%3}, [%4];"
                 : "=r"(r0), "=r"(r1), "=r"(r2), "=r"(r3) : "r"(a));
}
__device__ __forceinline__ void ldsm_x4t(uint32_t a, uint32_t& r0, uint32_t& r1,
                                         uint32_t& r2, uint32_t& r3) {
    asm volatile("ldmatrix.sync.aligned.m8n8.x4.trans.shared.b16 {%0,%1,%2,%3}, [%4];"
                 : "=r"(r0), "=r"(r1), "=r"(r2), "=r"(r3) : "r"(a));
}
__device__ __forceinline__ void mma16816h(uint32_t* c, uint32_t a0, uint32_t a1,
                                          uint32_t a2, uint32_t a3,
                                          uint32_t b0, uint32_t b1) {
    asm volatile(
        "mma.sync.aligned.m16n8k16.row.col.f16.f16.f16.f16 "
        "{%0,%1}, {%2,%3,%4,%5}, {%6,%7}, {%0,%1};"
        : "+r"(c[0]), "+r"(c[1])
        : "r"(a0), "r"(a1), "r"(a2), "r"(a3), "r"(b0), "r"(b1));
}
__device__ __forceinline__ int get_label(const int* l32, int i) { return l32[i * g_lblstride]; }

// ---------------- K1: normalize -> f16*sqrt(log2e) + class sums + resets ----
// 128 blocks x 256 threads; block b owns rows [64b, 64b+64).
__global__ void __launch_bounds__(256) k_normalize(const float* __restrict__ emb,
                                                   const int* __restrict__ l32) {
    const float SQRT_LOG2E = 1.2011224087864498f;
    int tid = threadIdx.x;
    int wid = tid >> 5, lane = tid & 31;
    int b = blockIdx.x;

    __shared__ int sdet;
    __shared__ float sM[2 * DDIM];
    __shared__ int   scnt[2];
    if (tid == 0) sdet = 0;
    sM[tid] = 0.0f;
    if (tid < 2) scnt[tid] = 0;
    __syncthreads();
    // labels are 0/1; int64 LE => odd int32 words are 0 (reads ints [1..511])
    if (l32[2 * tid + 1] != 0) atomicOr(&sdet, 1);
    __syncthreads();
    int stride = sdet ? 1 : 2;
    if (tid == 0 && b == 0) g_lblstride = stride;

    if (tid < 64) g_denom[b * 64 + tid] = 0.0f;

    #pragma unroll
    for (int it = 0; it < 8; it++) {
        int row = b * 64 + wid * 8 + it;
        float4 v = ((const float4*)(emb + (size_t)row * DDIM))[lane];
        float ss = v.x * v.x + v.y * v.y + v.z * v.z + v.w * v.w;
        #pragma unroll
        for (int o = 16; o; o >>= 1) ss += __shfl_xor_sync(0xffffffffu, ss, o);
        float r = rsqrtf(ss);
        int d = lane * 4;
        float e0 = v.x * r, e1 = v.y * r, e2 = v.z * r, e3 = v.w * r;
        float s = r * SQRT_LOG2E;
        __half2 h01 = __floats2half2_rn(v.x * s, v.y * s);
        __half2 h23 = __floats2half2_rn(v.z * s, v.w * s);
        *(__half2*)&g_h[(size_t)row * DDIM + d]     = h01;
        *(__half2*)&g_h[(size_t)row * DDIM + d + 2] = h23;
        int c = (l32[row * stride] == 0) ? 0 : 1;
        if (lane == 0) atomicAdd(&scnt[c], 1);
        float* sMc = &sM[c * DDIM + d];
        atomicAdd(&sMc[0], e0);
        atomicAdd(&sMc[1], e1);
        atomicAdd(&sMc[2], e2);
        atomicAdd(&sMc[3], e3);
    }
    __syncthreads();
    atomicAdd(&g_M[tid], sM[tid]);
    if (tid < 2) atomicAdd(&g_ncnt[tid], scnt[tid]);
}

// ---------------- K2: f16 HMMA, CTA 256(m)x128(n); warp-0-only loss tails ----
// grid (bj, bi2), valid when bj >= 2*bi2. Halves h=0,1 are i-tiles 2*bi2+h.
// 8 warps as 4(m) x 2(n), warp tile 64x64, f16 accumulators.
// After denom atomics, warps 1-7 EXIT; warp 0 alone runs tickets (one
// predicated ATOMG for 3 lanes) and any slab/final tails warp-collectively.
__global__ void __launch_bounds__(256, 2) k_sim(const int* __restrict__ l32,
                                                float* __restrict__ out) {
    int bj = blockIdx.x, bi2 = blockIdx.y;
    if (bj < 2 * bi2) return;

    extern __shared__ char smem[];
    uint32_t sb = smem_u32(smem);
    float* red  = (float*)(smem + SM_RED);
    float* redc = (float*)(smem + SM_REDC);

    int tid = threadIdx.x;
    int wid = tid >> 5, lane = tid & 31;
    int i0 = bi2 * 256, j0 = bj * 128;

    red[tid] = 0.0f;
    if (tid < 128) redc[tid] = 0.0f;

    // ---- tile loads (16B chunk c of row r stored at chunk c^(r&7)) ----
    {
        const uint4* arow = (const uint4*)&g_h[(size_t)(i0 + tid) * DDIM];
        #pragma unroll
        for (int c = 0; c < 16; c++) {
            uint32_t off = tid * 256 + ((c ^ (tid & 7)) << 4);
            *(uint4*)(smem + SM_A + off) = arow[c];
        }
        int row = tid >> 1, half = tid & 1;
        const uint4* brow = (const uint4*)&g_h[(size_t)(j0 + row) * DDIM];
        #pragma unroll
        for (int c = 0; c < 8; c++) {
            int chunk = half * 8 + c;
            uint32_t off = row * 256 + ((chunk ^ (row & 7)) << 4);
            *(uint4*)(smem + SM_B + off) = brow[chunk];
        }
    }
    __syncthreads();

    int mg = wid >> 1, ng = wid & 1;
    int m_off = mg * 64, n_off = ng * 64;
    int h = mg >> 1;
    bool skip = (bj == 2 * bi2) && (h == 1);
    bool diag = (2 * bi2 + h == bj);

    if (!skip) {
        uint32_t acc[4][8][2];
        #pragma unroll
        for (int mt = 0; mt < 4; mt++)
            #pragma unroll
            for (int nt = 0; nt < 8; nt++) { acc[mt][nt][0] = 0u; acc[mt][nt][1] = 0u; }

        uint32_t rowA = (uint32_t)(m_off + (lane & 15));
        uint32_t rowBbase = (uint32_t)(n_off + ((lane >> 4) << 3) + (lane & 7));
        uint32_t chA_sel = (uint32_t)(lane >> 4);
        uint32_t chB_sel = (uint32_t)((lane >> 3) & 1);

        #pragma unroll
        for (int kk = 0; kk < 8; kk++) {
            uint32_t a[4][4];
            #pragma unroll
            for (int mt = 0; mt < 4; mt++) {
                uint32_t r = rowA + mt * 16;
                uint32_t chunk = (uint32_t)(kk * 2) + chA_sel;
                uint32_t addr = sb + SM_A + r * 256 + ((chunk ^ (r & 7)) << 4);
                ldsm_x4(addr, a[mt][0], a[mt][1], a[mt][2], a[mt][3]);
            }
            uint32_t b[8][2];
            #pragma unroll
            for (int p = 0; p < 4; p++) {
                uint32_t r = rowBbase + (uint32_t)(p * 16);
                uint32_t chunk = (uint32_t)(kk * 2) + chB_sel;
                uint32_t addr = sb + SM_B + r * 256 + ((chunk ^ (r & 7)) << 4);
                ldsm_x4t(addr, b[2 * p][0], b[2 * p][1], b[2 * p + 1][0], b[2 * p + 1][1]);
            }
            #pragma unroll
            for (int mt = 0; mt < 4; mt++)
                #pragma unroll
                for (int nt = 0; nt < 8; nt++)
                    mma16816h(acc[mt][nt], a[mt][0], a[mt][1], a[mt][2], a[mt][3],
                              b[nt][0], b[nt][1]);
        }

        int lrow = lane >> 2;
        int lcol = (lane & 3) * 2;

        if (!diag) {
            // ---- f16x2 epilogue: ex2 on both halves, half2 partial sums ----
            uint32_t colp[8];
            #pragma unroll
            for (int nt = 0; nt < 8; nt++) colp[nt] = 0u;
            #pragma unroll
            for (int mt = 0; mt < 4; mt++) {
                uint32_t rp0 = 0u, rp1 = 0u;
                #pragma unroll
                for (int nt = 0; nt < 8; nt++) {
                    uint32_t e0 = h2exp2(acc[mt][nt][0]);
                    uint32_t e1 = h2exp2(acc[mt][nt][1]);
                    rp0 = h2add(rp0, e0);
                    rp1 = h2add(rp1, e1);
                    colp[nt] = h2add(colp[nt], h2add(e0, e1));
                }
                float2 f0 = h2tof2(rp0);
                float2 f1 = h2tof2(rp1);
                float s0 = f0.x + f0.y;
                float s1 = f1.x + f1.y;
                s0 += __shfl_xor_sync(0xffffffffu, s0, 1);
                s0 += __shfl_xor_sync(0xffffffffu, s0, 2);
                s1 += __shfl_xor_sync(0xffffffffu, s1, 1);
                s1 += __shfl_xor_sync(0xffffffffu, s1, 2);
                if ((lane & 3) == 0) {
                    atomicAdd(&red[m_off + mt * 16 + lrow], s0);
                    atomicAdd(&red[m_off + mt * 16 + lrow + 8], s1);
                }
            }
            #pragma unroll
            for (int nt = 0; nt < 8; nt++) {
                float2 cf = h2tof2(colp[nt]);
                #pragma unroll
                for (int hh = 0; hh < 2; hh++) {
                    float c = hh ? cf.y : cf.x;
                    c += __shfl_xor_sync(0xffffffffu, c, 4);
                    c += __shfl_xor_sync(0xffffffffu, c, 8);
                    c += __shfl_xor_sync(0xffffffffu, c, 16);
                    if (lane < 4)
                        atomicAdd(&redc[n_off + nt * 8 + (lane & 3) * 2 + hh], c);
                }
            }
        } else {
            // ---- diag slow path: fp32 with exact masking (no col sums) ----
            #pragma unroll
            for (int mt = 0; mt < 4; mt++) {
                float s0 = 0.0f, s1 = 0.0f;
                int grow0 = i0 + m_off + mt * 16 + lrow;
                #pragma unroll
                for (int nt = 0; nt < 8; nt++) {
                    int gcol = j0 + n_off + nt * 8 + lcol;
                    float2 f0 = h2tof2(acc[mt][nt][0]);
                    float2 f1 = h2tof2(acc[mt][nt][1]);
                    float e0 = ex2f(f0.x), e1 = ex2f(f0.y);
                    float e2 = ex2f(f1.x), e3 = ex2f(f1.y);
                    if (gcol     == grow0)     e0 = 0.0f;
                    if (gcol + 1 == grow0)     e1 = 0.0f;
                    if (gcol     == grow0 + 8) e2 = 0.0f;
                    if (gcol + 1 == grow0 + 8) e3 = 0.0f;
                    s0 += e0 + e1;
                    s1 += e2 + e3;
                }
                s0 += __shfl_xor_sync(0xffffffffu, s0, 1);
                s0 += __shfl_xor_sync(0xffffffffu, s0, 2);
                s1 += __shfl_xor_sync(0xffffffffu, s1, 1);
                s1 += __shfl_xor_sync(0xffffffffu, s1, 2);
                if ((lane & 3) == 0) {
                    atomicAdd(&red[m_off + mt * 16 + lrow], s0);
                    atomicAdd(&red[m_off + mt * 16 + lrow + 8], s1);
                }
            }
        }
    }

    __syncthreads();
    atomicAdd(&g_denom[i0 + tid], red[tid]);
    bool has_j = (bj != 2 * bi2);
    if (tid < 128 && has_j)
        atomicAdd(&g_denom[j0 + tid], redc[tid]);
    __syncthreads();                     // all denom atomics issued

    // ===== warps 1-7: done. warp 0 handles all tail work =====================
    if (wid != 0) return;

    // slab tickets: lanes 0-2 issue one predicated ATOMG (latencies overlap)
    int myslab = (lane == 0) ? 2 * bi2 : ((lane == 1) ? 2 * bi2 + 1 : bj);
    int thr    = (lane == 2) ? (64 - (bj >> 1)) : (64 - bi2);
    bool doatom = (lane == 0) || (lane < 3 && has_j);
    int cnt = -1;
    if (doatom) {
        __threadfence();
        cnt = atomicAdd(&g_slabcnt[myslab], 1);
    }
    unsigned finmask = __ballot_sync(0xffffffffu, doatom && (cnt == thr - 1));
    int nfin = __popc(finmask);
    if (nfin == 0) return;

    __threadfence();                     // acquire: slab contributions visible
    unsigned fm = finmask;
    while (fm) {
        int src = __ffs((int)fm) - 1;
        fm &= fm - 1;
        int s = __shfl_sync(0xffffffffu, myslab, src);
        float l0 = 0.0f, l1 = 0.0f;
        #pragma unroll
        for (int r4 = 0; r4 < 4; r4++) {
            int row = s * 128 + r4 * 32 + lane;
            float li = logf(g_denom[row]);
            if (get_label(l32, row) == 0) l0 += li; else l1 += li;
        }
        #pragma unroll
        for (int o = 16; o; o >>= 1) {
            l0 += __shfl_xor_sync(0xffffffffu, l0, o);
            l1 += __shfl_xor_sync(0xffffffffu, l1, o);
        }
        if (lane == 0) {
            g_Lpart[s][0] = l0;
            g_Lpart[s][1] = l1;
            g_slabcnt[s] = 0;                      // self-reset for next replay
        }
    }

    // final ticket
    int isfinal = 0;
    if (lane == 0) {
        __threadfence();
        int old = atomicAdd(&g_slabs, nfin);
        isfinal = (old + nfin == NTILE) ? 1 : 0;
        if (isfinal) g_slabs = 0;                  // self-reset
    }
    isfinal = __shfl_sync(0xffffffffu, isfinal, 0);
    if (!isfinal) return;
    __threadfence();

    // final assembly (warp-collective): |Mc|^2, sum Lparts, closed form
    float m0 = 0.0f, m1 = 0.0f;
    #pragma unroll
    for (int k = 0; k < 8; k++) {
        int t = k * 32 + lane;
        float v = g_M[t];
        g_M[t] = 0.0f;                             // self-reset
        if (t < 128) m0 += v * v; else m1 += v * v;
    }
    float L0 = 0.0f, L1 = 0.0f;
    #pragma unroll
    for (int k = 0; k < 2; k++) {
        int t = k * 32 + lane;
        L0 += g_Lpart[t][0];
        L1 += g_Lpart[t][1];
    }
    #pragma unroll
    for (int o = 16; o; o >>= 1) {
        m0 += __shfl_xor_sync(0xffffffffu, m0, o);
        m1 += __shfl_xor_sync(0xffffffffu, m1, o);
        L0 += __shfl_xor_sync(0xffffffffu, L0, o);
        L1 += __shfl_xor_sync(0xffffffffu, L1, o);
    }
    if (lane == 0) {
        float n0 = (float)g_ncnt[0], n1 = (float)g_ncnt[1];
        g_ncnt[0] = 0; g_ncnt[1] = 0;              // self-reset
        float loss0 = -m0 + n0 + (n0 - 1.0f) * L0;
        float loss1 = -m1 + n1 + (n1 - 1.0f) * L1;
        out[0] = loss0 / n0 + loss1;
    }
}

// ---------------- launch -----------------------------------------------------
extern "C" void kernel_launch(void* const* d_in, const int* in_sizes, int n_in,
                              void* d_out, int out_size) {
    const float* emb = (const float*)d_in[0];
    const int*   l32 = (const int*)d_in[1];
    float*       out = (float*)d_out;

    cudaFuncSetAttribute(k_sim, cudaFuncAttributeMaxDynamicSharedMemorySize, SM_TOT);

    k_normalize<<<128, 256>>>(emb, l32);
    dim3 grid(64, 32);                 // bj, bi2; invalid CTAs exit immediately
    k_sim<<<grid, 256, SM_TOT>>>(l32, out);
}

// round 17
// speedup vs baseline: 1.8055x; 1.6246x over previous
#include <cuda_runtime.h>
#include <cuda_fp16.h>
#include <math.h>
#include <cstdint>

#define NROWS 8192
#define DDIM  128
#define NTILE (NROWS / 128)               // 64 slabs of 128 rows

// dynamic smem layout for k_sim
#define SM_A    0                         // 256 rows x 256B f16 = 65536
#define SM_B    65536                     // 128 rows x 256B f16 = 32768
#define SM_RED  98304                     // 256 f32 row sums
#define SM_REDC 99328                     // 128 f32 col sums
#define SM_TOT  99840

// ---------------- scratch (init-free or self-resetting) ---------------------
__device__ __half g_h[NROWS * DDIM];      // normalized * sqrt(log2e), f16
__device__ float  g_denom[NROWS];         // zeroed by k_normalize each run
__device__ float  g_M[2 * DDIM];          // class sums; reset by final finisher
__device__ int    g_ncnt[2];              // class counts; reset by final finisher
__device__ float  g_Lpart[NTILE][2];      // per-slab gated log sums
__device__ int    g_slabcnt[NTILE];       // reset by slab finisher
__device__ int    g_slabs;                // reset by final finisher
__device__ int    g_lblstride;

// ---------------- helpers ----------------------------------------------------
__device__ __forceinline__ uint32_t smem_u32(const void* p) {
    uint32_t a;
    asm("{ .reg .u64 t; cvta.to.shared.u64 t, %1; cvt.u32.u64 %0, t; }" : "=r"(a) : "l"(p));
    return a;
}
__device__ __forceinline__ float ex2f(float x) {
    float r;
    asm("ex2.approx.ftz.f32 %0, %1;" : "=f"(r) : "f"(x));
    return r;
}
__device__ __forceinline__ uint32_t h2exp2(uint32_t x) {
    uint32_t r;
    asm("ex2.approx.f16x2 %0, %1;" : "=r"(r) : "r"(x));
    return r;
}
__device__ __forceinline__ uint32_t h2add(uint32_t a, uint32_t b) {
    uint32_t r;
    asm("add.rn.f16x2 %0, %1, %2;" : "=r"(r) : "r"(a), "r"(b));
    return r;
}
__device__ __forceinline__ float2 h2tof2(uint32_t h) {
    __half2 v = *(__half2*)&h;
    return __half22float2(v);
}
__device__ __forceinline__ void ldsm_x4(uint32_t a, uint32_t& r0, uint32_t& r1,
                                        uint32_t& r2, uint32_t& r3) {
    asm volatile("ldmatrix.sync.aligned.m8n8.x4.shared.b16 {%0,%1,%2,%3}, [%4];"
                 : "=r"(r0), "=r"(r1), "=r"(r2), "=r"(r3) : "r"(a));
}
__device__ __forceinline__ void ldsm_x4t(uint32_t a, uint32_t& r0, uint32_t& r1,
                                         uint32_t& r2, uint32_t& r3) {
    asm volatile("ldmatrix.sync.aligned.m8n8.x4.trans.shared.b16 {%0,%1,%2,%3}, [%4];"
                 : "=r"(r0), "=r"(r1), "=r"(r2), "=r"(r3) : "r"(a));
}
__device__ __forceinline__ void mma16816h(uint32_t* c, uint32_t a0, uint32_t a1,
                                          uint32_t a2, uint32_t a3,
                                          uint32_t b0, uint32_t b1) {
    asm volatile(
        "mma.sync.aligned.m16n8k16.row.col.f16.f16.f16.f16 "
        "{%0,%1}, {%2,%3,%4,%5}, {%6,%7}, {%0,%1};"
        : "+r"(c[0]), "+r"(c[1])
        : "r"(a0), "r"(a1), "r"(a2), "r"(a3), "r"(b0), "r"(b1));
}
__device__ __forceinline__ int get_label(const int* l32, int i) { return l32[i * g_lblstride]; }

// ---------------- K1: normalize -> f16*sqrt(log2e) + class sums + resets ----
// 128 blocks x 256 threads; block b owns rows [64b, 64b+64).
__global__ void __launch_bounds__(256) k_normalize(const float* __restrict__ emb,
                                                   const int* __restrict__ l32) {
    const float SQRT_LOG2E = 1.2011224087864498f;
    int tid = threadIdx.x;
    int wid = tid >> 5, lane = tid & 31;
    int b = blockIdx.x;

    __shared__ int sdet;
    __shared__ float sM[2 * DDIM];
    __shared__ int   scnt[2];
    if (tid == 0) sdet = 0;
    sM[tid] = 0.0f;
    if (tid < 2) scnt[tid] = 0;
    __syncthreads();
    // labels are 0/1; int64 LE => odd int32 words are 0 (reads ints [1..511])
    if (l32[2 * tid + 1] != 0) atomicOr(&sdet, 1);
    __syncthreads();
    int stride = sdet ? 1 : 2;
    if (tid == 0 && b == 0) g_lblstride = stride;

    if (tid < 64) g_denom[b * 64 + tid] = 0.0f;

    #pragma unroll
    for (int it = 0; it < 8; it++) {
        int row = b * 64 + wid * 8 + it;
        float4 v = ((const float4*)(emb + (size_t)row * DDIM))[lane];
        float ss = v.x * v.x + v.y * v.y + v.z * v.z + v.w * v.w;
        #pragma unroll
        for (int o = 16; o; o >>= 1) ss += __shfl_xor_sync(0xffffffffu, ss, o);
        float r = rsqrtf(ss);
        int d = lane * 4;
        float e0 = v.x * r, e1 = v.y * r, e2 = v.z * r, e3 = v.w * r;
        float s = r * SQRT_LOG2E;
        __half2 h01 = __floats2half2_rn(v.x * s, v.y * s);
        __half2 h23 = __floats2half2_rn(v.z * s, v.w * s);
        *(__half2*)&g_h[(size_t)row * DDIM + d]     = h01;
        *(__half2*)&g_h[(size_t)row * DDIM + d + 2] = h23;
        int c = (l32[row * stride] == 0) ? 0 : 1;
        if (lane == 0) atomicAdd(&scnt[c], 1);
        float* sMc = &sM[c * DDIM + d];
        atomicAdd(&sMc[0], e0);
        atomicAdd(&sMc[1], e1);
        atomicAdd(&sMc[2], e2);
        atomicAdd(&sMc[3], e3);
    }
    __syncthreads();
    atomicAdd(&g_M[tid], sM[tid]);
    if (tid < 2) atomicAdd(&g_ncnt[tid], scnt[tid]);
}

// ---------------- K2: f16 HMMA, CTA 256(m)x128(n); warp-0-only loss tails ----
// grid (bj, bi2), valid when bj >= 2*bi2. Halves h=0,1 are i-tiles 2*bi2+h.
// 8 warps as 4(m) x 2(n), warp tile 64x64, f16 accumulators.
// Tile loads: COALESCED cp.async (16B chunks; warp covers contiguous 512B).
__global__ void __launch_bounds__(256, 2) k_sim(const int* __restrict__ l32,
                                                float* __restrict__ out) {
    int bj = blockIdx.x, bi2 = blockIdx.y;
    if (bj < 2 * bi2) return;

    extern __shared__ char smem[];
    uint32_t sb = smem_u32(smem);
    float* red  = (float*)(smem + SM_RED);
    float* redc = (float*)(smem + SM_REDC);

    int tid = threadIdx.x;
    int wid = tid >> 5, lane = tid & 31;
    int i0 = bi2 * 256, j0 = bj * 128;

    // ---- tile loads: coalesced cp.async (chunk f: row=f>>4, ch=f&15) ----
    #pragma unroll
    for (int it = 0; it < 16; it++) {
        int f = it * 256 + tid;
        int row = f >> 4, ch = f & 15;
        uint32_t off = (uint32_t)(row * 256 + ((ch ^ (row & 7)) << 4));
        const __half* ga = &g_h[(size_t)(i0 + row) * DDIM + ch * 8];
        asm volatile("cp.async.cg.shared.global [%0], [%1], 16;"
                     :: "r"(sb + SM_A + off), "l"(ga));
    }
    #pragma unroll
    for (int it = 0; it < 8; it++) {
        int f = it * 256 + tid;
        int row = f >> 4, ch = f & 15;
        uint32_t off = (uint32_t)(row * 256 + ((ch ^ (row & 7)) << 4));
        const __half* gb = &g_h[(size_t)(j0 + row) * DDIM + ch * 8];
        asm volatile("cp.async.cg.shared.global [%0], [%1], 16;"
                     :: "r"(sb + SM_B + off), "l"(gb));
    }
    asm volatile("cp.async.commit_group;" ::: "memory");

    red[tid] = 0.0f;
    if (tid < 128) redc[tid] = 0.0f;

    asm volatile("cp.async.wait_group 0;" ::: "memory");
    __syncthreads();

    int mg = wid >> 1, ng = wid & 1;
    int m_off = mg * 64, n_off = ng * 64;
    int h = mg >> 1;
    bool skip = (bj == 2 * bi2) && (h == 1);
    bool diag = (2 * bi2 + h == bj);

    if (!skip) {
        uint32_t acc[4][8][2];
        #pragma unroll
        for (int mt = 0; mt < 4; mt++)
            #pragma unroll
            for (int nt = 0; nt < 8; nt++) { acc[mt][nt][0] = 0u; acc[mt][nt][1] = 0u; }

        uint32_t rowA = (uint32_t)(m_off + (lane & 15));
        uint32_t rowBbase = (uint32_t)(n_off + ((lane >> 4) << 3) + (lane & 7));
        uint32_t chA_sel = (uint32_t)(lane >> 4);
        uint32_t chB_sel = (uint32_t)((lane >> 3) & 1);

        #pragma unroll
        for (int kk = 0; kk < 8; kk++) {
            uint32_t a[4][4];
            #pragma unroll
            for (int mt = 0; mt < 4; mt++) {
                uint32_t r = rowA + mt * 16;
                uint32_t chunk = (uint32_t)(kk * 2) + chA_sel;
                uint32_t addr = sb + SM_A + r * 256 + ((chunk ^ (r & 7)) << 4);
                ldsm_x4(addr, a[mt][0], a[mt][1], a[mt][2], a[mt][3]);
            }
            uint32_t b[8][2];
            #pragma unroll
            for (int p = 0; p < 4; p++) {
                uint32_t r = rowBbase + (uint32_t)(p * 16);
                uint32_t chunk = (uint32_t)(kk * 2) + chB_sel;
                uint32_t addr = sb + SM_B + r * 256 + ((chunk ^ (r & 7)) << 4);
                ldsm_x4t(addr, b[2 * p][0], b[2 * p][1], b[2 * p + 1][0], b[2 * p + 1][1]);
            }
            #pragma unroll
            for (int mt = 0; mt < 4; mt++)
                #pragma unroll
                for (int nt = 0; nt < 8; nt++)
                    mma16816h(acc[mt][nt], a[mt][0], a[mt][1], a[mt][2], a[mt][3],
                              b[nt][0], b[nt][1]);
        }

        int lrow = lane >> 2;
        int lcol = (lane & 3) * 2;

        if (!diag) {
            // ---- f16x2 epilogue: ex2 on both halves, half2 partial sums ----
            uint32_t colp[8];
            #pragma unroll
            for (int nt = 0; nt < 8; nt++) colp[nt] = 0u;
            #pragma unroll
            for (int mt = 0; mt < 4; mt++) {
                uint32_t rp0 = 0u, rp1 = 0u;
                #pragma unroll
                for (int nt = 0; nt < 8; nt++) {
                    uint32_t e0 = h2exp2(acc[mt][nt][0]);
                    uint32_t e1 = h2exp2(acc[mt][nt][1]);
                    rp0 = h2add(rp0, e0);
                    rp1 = h2add(rp1, e1);
                    colp[nt] = h2add(colp[nt], h2add(e0, e1));
                }
                float2 f0 = h2tof2(rp0);
                float2 f1 = h2tof2(rp1);
                float s0 = f0.x + f0.y;
                float s1 = f1.x + f1.y;
                s0 += __shfl_xor_sync(0xffffffffu, s0, 1);
                s0 += __shfl_xor_sync(0xffffffffu, s0, 2);
                s1 += __shfl_xor_sync(0xffffffffu, s1, 1);
                s1 += __shfl_xor_sync(0xffffffffu, s1, 2);
                if ((lane & 3) == 0) {
                    atomicAdd(&red[m_off + mt * 16 + lrow], s0);
                    atomicAdd(&red[m_off + mt * 16 + lrow + 8], s1);
                }
            }
            #pragma unroll
            for (int nt = 0; nt < 8; nt++) {
                float2 cf = h2tof2(colp[nt]);
                #pragma unroll
                for (int hh = 0; hh < 2; hh++) {
                    float c = hh ? cf.y : cf.x;
                    c += __shfl_xor_sync(0xffffffffu, c, 4);
                    c += __shfl_xor_sync(0xffffffffu, c, 8);
                    c += __shfl_xor_sync(0xffffffffu, c, 16);
                    if (lane < 4)
                        atomicAdd(&redc[n_off + nt * 8 + (lane & 3) * 2 + hh], c);
                }
            }
        } else {
            // ---- diag slow path: fp32 with exact masking (no col sums) ----
            #pragma unroll
            for (int mt = 0; mt < 4; mt++) {
                float s0 = 0.0f, s1 = 0.0f;
                int grow0 = i0 + m_off + mt * 16 + lrow;
                #pragma unroll
                for (int nt = 0; nt < 8; nt++) {
                    int gcol = j0 + n_off + nt * 8 + lcol;
                    float2 f0 = h2tof2(acc[mt][nt][0]);
                    float2 f1 = h2tof2(acc[mt][nt][1]);
                    float e0 = ex2f(f0.x), e1 = ex2f(f0.y);
                    float e2 = ex2f(f1.x), e3 = ex2f(f1.y);
                    if (gcol     == grow0)     e0 = 0.0f;
                    if (gcol + 1 == grow0)     e1 = 0.0f;
                    if (gcol     == grow0 + 8) e2 = 0.0f;
                    if (gcol + 1 == grow0 + 8) e3 = 0.0f;
                    s0 += e0 + e1;
                    s1 += e2 + e3;
                }
                s0 += __shfl_xor_sync(0xffffffffu, s0, 1);
                s0 += __shfl_xor_sync(0xffffffffu, s0, 2);
                s1 += __shfl_xor_sync(0xffffffffu, s1, 1);
                s1 += __shfl_xor_sync(0xffffffffu, s1, 2);
                if ((lane & 3) == 0) {
                    atomicAdd(&red[m_off + mt * 16 + lrow], s0);
                    atomicAdd(&red[m_off + mt * 16 + lrow + 8], s1);
                }
            }
        }
    }

    __syncthreads();
    atomicAdd(&g_denom[i0 + tid], red[tid]);
    bool has_j = (bj != 2 * bi2);
    if (tid < 128 && has_j)
        atomicAdd(&g_denom[j0 + tid], redc[tid]);
    __syncthreads();                     // all denom atomics issued

    // ===== warps 1-7: done. warp 0 handles all tail work =====================
    if (wid != 0) return;

    // slab tickets: lanes 0-2 issue one predicated ATOMG (latencies overlap)
    int myslab = (lane == 0) ? 2 * bi2 : ((lane == 1) ? 2 * bi2 + 1 : bj);
    int thr    = (lane == 2) ? (64 - (bj >> 1)) : (64 - bi2);
    bool doatom = (lane == 0) || (lane < 3 && has_j);
    int cnt = -1;
    if (doatom) {
        __threadfence();
        cnt = atomicAdd(&g_slabcnt[myslab], 1);
    }
    unsigned finmask = __ballot_sync(0xffffffffu, doatom && (cnt == thr - 1));
    int nfin = __popc(finmask);
    if (nfin == 0) return;

    __threadfence();                     // acquire: slab contributions visible
    unsigned fm = finmask;
    while (fm) {
        int src = __ffs((int)fm) - 1;
        fm &= fm - 1;
        int s = __shfl_sync(0xffffffffu, myslab, src);
        float l0 = 0.0f, l1 = 0.0f;
        #pragma unroll
        for (int r4 = 0; r4 < 4; r4++) {
            int row = s * 128 + r4 * 32 + lane;
            float li = logf(g_denom[row]);
            if (get_label(l32, row) == 0) l0 += li; else l1 += li;
        }
        #pragma unroll
        for (int o = 16; o; o >>= 1) {
            l0 += __shfl_xor_sync(0xffffffffu, l0, o);
            l1 += __shfl_xor_sync(0xffffffffu, l1, o);
        }
        if (lane == 0) {
            g_Lpart[s][0] = l0;
            g_Lpart[s][1] = l1;
            g_slabcnt[s] = 0;                      // self-reset for next replay
        }
    }

    // final ticket
    int isfinal = 0;
    if (lane == 0) {
        __threadfence();
        int old = atomicAdd(&g_slabs, nfin);
        isfinal = (old + nfin == NTILE) ? 1 : 0;
        if (isfinal) g_slabs = 0;                  // self-reset
    }
    isfinal = __shfl_sync(0xffffffffu, isfinal, 0);
    if (!isfinal) return;
    __threadfence();

    // final assembly (warp-collective): |Mc|^2, sum Lparts, closed form
    float m0 = 0.0f, m1 = 0.0f;
    #pragma unroll
    for (int k = 0; k < 8; k++) {
        int t = k * 32 + lane;
        float v = g_M[t];
        g_M[t] = 0.0f;                             // self-reset
        if (t < 128) m0 += v * v; else m1 += v * v;
    }
    float L0 = 0.0f, L1 = 0.0f;
    #pragma unroll
    for (int k = 0; k < 2; k++) {
        int t = k * 32 + lane;
        L0 += g_Lpart[t][0];
        L1 += g_Lpart[t][1];
    }
    #pragma unroll
    for (int o = 16; o; o >>= 1) {
        m0 += __shfl_xor_sync(0xffffffffu, m0, o);
        m1 += __shfl_xor_sync(0xffffffffu, m1, o);
        L0 += __shfl_xor_sync(0xffffffffu, L0, o);
        L1 += __shfl_xor_sync(0xffffffffu, L1, o);
    }
    if (lane == 0) {
        float n0 = (float)g_ncnt[0], n1 = (float)g_ncnt[1];
        g_ncnt[0] = 0; g_ncnt[1] = 0;              // self-reset
        float loss0 = -m0 + n0 + (n0 - 1.0f) * L0;
        float loss1 = -m1 + n1 + (n1 - 1.0f) * L1;
        out[0] = loss0 / n0 + loss1;
    }
}

// ---------------- launch -----------------------------------------------------
extern "C" void kernel_launch(void* const* d_in, const int* in_sizes, int n_in,
                              void* d_out, int out_size) {
    const float* emb = (const float*)d_in[0];
    const int*   l32 = (const int*)d_in[1];
    float*       out = (float*)d_out;

    cudaFuncSetAttribute(k_sim, cudaFuncAttributeMaxDynamicSharedMemorySize, SM_TOT);

    k_normalize<<<128, 256>>>(emb, l32);
    dim3 grid(64, 32);                 // bj, bi2; invalid CTAs exit immediately
    k_sim<<<grid, 256, SM_TOT>>>(l32, out);
}